// round 11
// baseline (speedup 1.0000x reference)
#include <cuda_runtime.h>
#include <cuda_bf16.h>
#include <cuda_fp16.h>
#include <cstdint>

// ---------------- problem dims ----------------
#define MM 16384
#define DD 512
#define UU 512
#define KK 1024
#define NN 2048

// ---------------- GEMM tiling ----------------
#define BM 128
#define BN 128
#define BK 32
#define NKT (KK / BK)            // 32
#define NSTAGES 4
#define LDT 40                   // fp16 tile leading dim (halfwords): 80B rows
#define NTILES ((MM / BM) * (NN / BN))  // 2048
#define NCTAS 296                // 148 SMs x 2 CTAs

// ---------------- device scratch ----------------
__device__ __align__(16) __half g_A[(size_t)MM * KK];    // fp16(a)
__device__ __align__(16) __half g_Bhi[(size_t)NN * KK];  // fp16(b), permuted rows

// ---------------- prep A ----------------
__global__ void __launch_bounds__(256) prep_A_kernel(const float* __restrict__ x,
                                                     const float* __restrict__ h) {
    int gi = blockIdx.x * 256 + threadIdx.x;
    int b = gi >> 7;
    int k0 = (gi & 127) * 8;
    const float* src = (k0 < DD) ? (x + (size_t)b * DD + k0)
                                 : (h + (size_t)b * UU + (k0 - DD));
    float4 v0 = *reinterpret_cast<const float4*>(src);
    float4 v1 = *reinterpret_cast<const float4*>(src + 4);
    float v[8] = {v0.x, v0.y, v0.z, v0.w, v1.x, v1.y, v1.z, v1.w};
    __half hh[8];
#pragma unroll
    for (int j = 0; j < 8; j++) hh[j] = __float2half_rn(v[j]);
    *reinterpret_cast<uint4*>(&g_A[(size_t)b * KK + k0]) = *reinterpret_cast<uint4*>(hh);
}

// ---------------- prep B: transpose + permute (p = u*4 + gate) ----------------
__global__ void prep_B_kernel(const float* __restrict__ Wk, const float* __restrict__ Wr) {
    __shared__ float t[32][33];
    int n0 = blockIdx.x * 32, k0 = blockIdx.y * 32;
    int tn = threadIdx.x, tk = threadIdx.y;  // block (32, 8)
#pragma unroll
    for (int j = 0; j < 32; j += 8) {
        int k = k0 + tk + j;
        float v = (k < DD) ? Wk[(size_t)k * NN + n0 + tn]
                           : Wr[(size_t)(k - DD) * NN + n0 + tn];
        t[tk + j][tn] = v;
    }
    __syncthreads();
#pragma unroll
    for (int j = 0; j < 32; j += 8) {
        int n = n0 + tk + j;
        int k = k0 + tn;
        int p = ((n & 511) << 2) + (n >> 9);  // unit*4 + gate
        g_Bhi[(size_t)p * KK + k] = __float2half_rn(t[tn][tk + j]);
    }
}

// ---------------- fused GEMM (persistent, cross-tile pipeline) + gates ----------------
struct Stage {
    __half A[BM * LDT];     // 10240 B
    __half Bhi[BN * LDT];   // 10240 B
};  // 20480 B

#define LDZ 132                                        // multiple of 4 -> float4-aligned rows
#define ZBUF_B (64 * LDZ * 4)                          // 33792 B
#define SMEM_TOTAL (NSTAGES * sizeof(Stage) + ZBUF_B)  // 115712 B

__device__ __forceinline__ void cp_async16(void* dst, const void* src) {
    unsigned d = (unsigned)__cvta_generic_to_shared(dst);
    asm volatile("cp.async.cg.shared.global [%0], [%1], 16;" :: "r"(d), "l"(src) : "memory");
}

__device__ __forceinline__ void ldsm_x4(unsigned r[4], uint32_t addr) {
    asm volatile("ldmatrix.sync.aligned.m8n8.x4.shared.b16 {%0,%1,%2,%3}, [%4];"
                 : "=r"(r[0]), "=r"(r[1]), "=r"(r[2]), "=r"(r[3]) : "r"(addr));
}

__device__ __forceinline__ void mma_f16(float c[4], const unsigned a[4],
                                        unsigned b0, unsigned b1) {
    asm volatile(
        "mma.sync.aligned.m16n8k16.row.col.f32.f16.f16.f32 "
        "{%0,%1,%2,%3}, {%4,%5,%6,%7}, {%8,%9}, {%0,%1,%2,%3};"
        : "+f"(c[0]), "+f"(c[1]), "+f"(c[2]), "+f"(c[3])
        : "r"(a[0]), "r"(a[1]), "r"(a[2]), "r"(a[3]), "r"(b0), "r"(b1));
}

__device__ __forceinline__ float sigf(float x) { return 1.0f / (1.0f + __expf(-x)); }

__global__ void __launch_bounds__(256, 2)
lstm_gemm_kernel(const float* __restrict__ c_tm1,
                 const float* __restrict__ pw,
                 const float* __restrict__ bias,
                 float* __restrict__ out) {
    extern __shared__ __align__(16) unsigned char smem_raw[];
    Stage* stages = reinterpret_cast<Stage*>(smem_raw);
    float* zsm = reinterpret_cast<float*>(smem_raw + NSTAGES * sizeof(Stage));

    const int tid = threadIdx.x;
    const int lane = tid & 31;
    const int wid = tid >> 5;        // 0..7
    const int mw = (wid >> 1) * 32;  // 4 warps in M
    const int nw = (wid & 1) * 64;   // 2 warps in N
    const int bid = blockIdx.x;
    const int grid = gridDim.x;
    const int r = lane >> 2, q = lane & 3;

    const int lrow = (lane & 7) + ((lane >> 3) & 1) * 8;
    const int lkof = (lane >> 4) * 16;  // bytes

    // issue loads for global pipeline position gpos (tile-major, kt-minor)
    auto issue_pos = [&](int gpos) {
        int lti = gpos >> 5;
        int ltile = bid + lti * grid;
        if (ltile < NTILES) {
            int lm0 = (ltile >> 4) * BM;
            int ln0 = (ltile & 15) * BN;
            int k0 = (gpos & 31) * BK;
            Stage* st = &stages[gpos & (NSTAGES - 1)];
#pragma unroll
            for (int i = 0; i < 2; i++) {
                int c = tid + i * 256;
                int row = c >> 2, seg = c & 3;
                cp_async16(&st->A[row * LDT + seg * 8],
                           &g_A[(size_t)(lm0 + row) * KK + k0 + seg * 8]);
                cp_async16(&st->Bhi[row * LDT + seg * 8],
                           &g_Bhi[(size_t)(ln0 + row) * KK + k0 + seg * 8]);
            }
        }
        asm volatile("cp.async.commit_group;" ::: "memory");
    };

#pragma unroll
    for (int i = 0; i < NSTAGES - 1; i++) issue_pos(i);

    int pos = 0;
    for (int tile = bid; tile < NTILES; tile += grid) {
        const int m0 = (tile >> 4) * BM;
        const int nt = tile & 15;

        float acc[2][8][4];
#pragma unroll
        for (int a = 0; a < 2; a++)
#pragma unroll
            for (int b = 0; b < 8; b++)
#pragma unroll
                for (int c = 0; c < 4; c++) acc[a][b][c] = 0.0f;

        for (int kt = 0; kt < NKT; kt++, pos++) {
            asm volatile("cp.async.wait_group %0;" :: "n"(NSTAGES - 2) : "memory");
            __syncthreads();
            issue_pos(pos + NSTAGES - 1);

            const Stage* st = &stages[pos & (NSTAGES - 1)];
#pragma unroll
            for (int kk = 0; kk < BK; kk += 16) {
                unsigned ah[2][4];
#pragma unroll
                for (int ms = 0; ms < 2; ms++) {
                    uint32_t boff = (uint32_t)(((mw + ms * 16 + lrow) * LDT + kk) * 2 + lkof);
                    ldsm_x4(ah[ms], (unsigned)__cvta_generic_to_shared(
                                        (const char*)st->A + boff));
                }
#pragma unroll
                for (int p = 0; p < 4; p++) {
                    uint32_t boff = (uint32_t)(((nw + p * 16 + lrow) * LDT + kk) * 2 + lkof);
                    unsigned bh[4];
                    ldsm_x4(bh, (unsigned)__cvta_generic_to_shared(
                                    (const char*)st->Bhi + boff));
#pragma unroll
                    for (int e = 0; e < 2; e++)
#pragma unroll
                        for (int ms = 0; ms < 2; ms++)
                            mma_f16(acc[ms][p * 2 + e], ah[ms], bh[e], bh[e + 2]);
                }
            }
        }

        // ---- epilogue: two 64-row halves through separate z smem ----
        const int ul = tid & 31;
        const int u = nt * 32 + ul;
        const float bi = bias[u];
        const float bf = bias[512 + u];
        const float bg = bias[1024 + u];
        const float bo = bias[1536 + u];
        const float pwi = pw[u * 3 + 0];
        const float pwf = pw[u * 3 + 1];
        const float pwo = pw[u * 3 + 2];

#pragma unroll
        for (int hh = 0; hh < 2; hh++) {
            __syncthreads();  // previous half's reads (or prev tile) done
            if ((mw >> 6) == hh) {
                int rb = mw & 63;
#pragma unroll
                for (int ms = 0; ms < 2; ms++)
#pragma unroll
                    for (int ns = 0; ns < 8; ns++) {
                        int row = rb + ms * 16 + r;
                        int col = nw + ns * 8 + 2 * q;
                        *(float2*)&zsm[row * LDZ + col] =
                            make_float2(acc[ms][ns][0], acc[ms][ns][1]);
                        *(float2*)&zsm[(row + 8) * LDZ + col] =
                            make_float2(acc[ms][ns][2], acc[ms][ns][3]);
                    }
            }
            __syncthreads();
#pragma unroll
            for (int it = 0; it < 8; it++) {
                int row = (tid >> 5) * 8 + it;
                int m = m0 + hh * 64 + row;
                float4 zz = *reinterpret_cast<const float4*>(&zsm[row * LDZ + ul * 4]);
                float cprev = c_tm1[(size_t)m * UU + u];
                float iv = sigf(zz.x + bi + cprev * pwi);
                float fv = sigf(zz.y + bf + cprev * pwf);
                float gv = tanhf(zz.z + bg);
                float cc = fv * cprev + iv * gv;
                float ov = sigf(zz.w + bo + cc * pwo);
                out[(size_t)m * UU + u] = ov * tanhf(cc);
                out[(size_t)MM * UU + (size_t)m * UU + u] = cc;
            }
        }
    }
}

// ---------------- launch ----------------
extern "C" void kernel_launch(void* const* d_in, const int* in_sizes, int n_in,
                              void* d_out, int out_size) {
    const float* x    = (const float*)d_in[0];
    const float* h    = (const float*)d_in[1];
    const float* c    = (const float*)d_in[2];
    const float* Wk   = (const float*)d_in[3];
    const float* Wr   = (const float*)d_in[4];
    const float* pw   = (const float*)d_in[5];
    const float* bias = (const float*)d_in[6];
    float* out = (float*)d_out;

    cudaFuncSetAttribute(lstm_gemm_kernel, cudaFuncAttributeMaxDynamicSharedMemorySize,
                         (int)SMEM_TOTAL);

    prep_A_kernel<<<(MM * KK / 8) / 256, 256>>>(x, h);
    prep_B_kernel<<<dim3(NN / 32, KK / 32), dim3(32, 8)>>>(Wk, Wr);
    lstm_gemm_kernel<<<NCTAS, 256, SMEM_TOTAL>>>(c, pw, bias, out);
}

// round 12
// speedup vs baseline: 1.0821x; 1.0821x over previous
#include <cuda_runtime.h>
#include <cuda_bf16.h>
#include <cuda_fp16.h>
#include <cstdint>

// ---------------- problem dims ----------------
#define MM 16384
#define DD 512
#define UU 512
#define KK 1024
#define NN 2048

// ---------------- GEMM tiling ----------------
#define BM 128
#define BN 128
#define BK 32
#define NKT (KK / BK)            // 32
#define NSTAGES 5                // ring of 5, consumed 2 per barrier
#define LDT 40                   // fp16 tile leading dim (halfwords): 80B rows

// ---------------- device scratch ----------------
__device__ __align__(16) __half g_A[(size_t)MM * KK];    // fp16(a)
__device__ __align__(16) __half g_Bhi[(size_t)NN * KK];  // fp16(b), permuted rows

// ---------------- prep A ----------------
__global__ void __launch_bounds__(256) prep_A_kernel(const float* __restrict__ x,
                                                     const float* __restrict__ h) {
    int gi = blockIdx.x * 256 + threadIdx.x;
    int b = gi >> 7;
    int k0 = (gi & 127) * 8;
    const float* src = (k0 < DD) ? (x + (size_t)b * DD + k0)
                                 : (h + (size_t)b * UU + (k0 - DD));
    float4 v0 = *reinterpret_cast<const float4*>(src);
    float4 v1 = *reinterpret_cast<const float4*>(src + 4);
    float v[8] = {v0.x, v0.y, v0.z, v0.w, v1.x, v1.y, v1.z, v1.w};
    __half hh[8];
#pragma unroll
    for (int j = 0; j < 8; j++) hh[j] = __float2half_rn(v[j]);
    *reinterpret_cast<uint4*>(&g_A[(size_t)b * KK + k0]) = *reinterpret_cast<uint4*>(hh);
}

// ---------------- prep B: transpose + permute (p = u*4 + gate) ----------------
__global__ void prep_B_kernel(const float* __restrict__ Wk, const float* __restrict__ Wr) {
    __shared__ float t[32][33];
    int n0 = blockIdx.x * 32, k0 = blockIdx.y * 32;
    int tn = threadIdx.x, tk = threadIdx.y;  // block (32, 8)
#pragma unroll
    for (int j = 0; j < 32; j += 8) {
        int k = k0 + tk + j;
        float v = (k < DD) ? Wk[(size_t)k * NN + n0 + tn]
                           : Wr[(size_t)(k - DD) * NN + n0 + tn];
        t[tk + j][tn] = v;
    }
    __syncthreads();
#pragma unroll
    for (int j = 0; j < 32; j += 8) {
        int n = n0 + tk + j;
        int k = k0 + tn;
        int p = ((n & 511) << 2) + (n >> 9);  // unit*4 + gate
        g_Bhi[(size_t)p * KK + k] = __float2half_rn(t[tn][tk + j]);
    }
}

// ---------------- fused GEMM (single-pass f16, paired-stage sync) + gates ----------------
struct Stage {
    __half A[BM * LDT];     // 10240 B
    __half Bhi[BN * LDT];   // 10240 B
};  // 20480 B

__device__ __forceinline__ void cp_async16(void* dst, const void* src) {
    unsigned d = (unsigned)__cvta_generic_to_shared(dst);
    asm volatile("cp.async.cg.shared.global [%0], [%1], 16;" :: "r"(d), "l"(src) : "memory");
}

__device__ __forceinline__ void ldsm_x4(unsigned r[4], uint32_t addr) {
    asm volatile("ldmatrix.sync.aligned.m8n8.x4.shared.b16 {%0,%1,%2,%3}, [%4];"
                 : "=r"(r[0]), "=r"(r[1]), "=r"(r[2]), "=r"(r[3]) : "r"(addr));
}

__device__ __forceinline__ void mma_f16(float c[4], const unsigned a[4],
                                        unsigned b0, unsigned b1) {
    asm volatile(
        "mma.sync.aligned.m16n8k16.row.col.f32.f16.f16.f32 "
        "{%0,%1,%2,%3}, {%4,%5,%6,%7}, {%8,%9}, {%0,%1,%2,%3};"
        : "+f"(c[0]), "+f"(c[1]), "+f"(c[2]), "+f"(c[3])
        : "r"(a[0]), "r"(a[1]), "r"(a[2]), "r"(a[3]), "r"(b0), "r"(b1));
}

__device__ __forceinline__ float sigf(float x) { return 1.0f / (1.0f + __expf(-x)); }

#define LDZ 132  // padded z stride in floats (multiple of 4: float4-aligned rows)

__global__ void __launch_bounds__(256, 2)
lstm_gemm_kernel(const float* __restrict__ c_tm1,
                 const float* __restrict__ pw,
                 const float* __restrict__ bias,
                 float* __restrict__ out) {
    extern __shared__ __align__(16) unsigned char smem_raw[];
    Stage* stages = reinterpret_cast<Stage*>(smem_raw);

    const int tid = threadIdx.x;
    const int lane = tid & 31;
    const int wid = tid >> 5;        // 0..7
    const int mw = (wid >> 1) * 32;  // 4 warps in M
    const int nw = (wid & 1) * 64;   // 2 warps in N
    const int m0 = blockIdx.y * BM;
    const int n0 = blockIdx.x * BN;
    const int r = lane >> 2, q = lane & 3;

    const int lrow = (lane & 7) + ((lane >> 3) & 1) * 8;
    const int lkof = (lane >> 4) * 16;  // bytes

    // issue loads for k-stage s into ring slot s % NSTAGES; one commit per call
    auto issue_stage = [&](int s) {
        if (s < NKT) {
            Stage* st = &stages[s % NSTAGES];
            int k0 = s * BK;
#pragma unroll
            for (int i = 0; i < 2; i++) {
                int c = tid + i * 256;
                int row = c >> 2, seg = c & 3;
                cp_async16(&st->A[row * LDT + seg * 8],
                           &g_A[(size_t)(m0 + row) * KK + k0 + seg * 8]);
                cp_async16(&st->Bhi[row * LDT + seg * 8],
                           &g_Bhi[(size_t)(n0 + row) * KK + k0 + seg * 8]);
            }
        }
        asm volatile("cp.async.commit_group;" ::: "memory");
    };

    float acc[2][8][4];
#pragma unroll
    for (int a = 0; a < 2; a++)
#pragma unroll
        for (int b = 0; b < 8; b++)
#pragma unroll
            for (int c = 0; c < 4; c++) acc[a][b][c] = 0.0f;

    issue_stage(0);
    issue_stage(1);
    issue_stage(2);

    // compute one k-stage from ring slot
    auto compute_stage = [&](int s) {
        const Stage* st = &stages[s % NSTAGES];
#pragma unroll
        for (int kk = 0; kk < BK; kk += 16) {
            unsigned ah[2][4];
#pragma unroll
            for (int ms = 0; ms < 2; ms++) {
                uint32_t boff = (uint32_t)(((mw + ms * 16 + lrow) * LDT + kk) * 2 + lkof);
                ldsm_x4(ah[ms], (unsigned)__cvta_generic_to_shared(
                                    (const char*)st->A + boff));
            }
#pragma unroll
            for (int p = 0; p < 4; p++) {
                uint32_t boff = (uint32_t)(((nw + p * 16 + lrow) * LDT + kk) * 2 + lkof);
                unsigned bh[4];
                ldsm_x4(bh, (unsigned)__cvta_generic_to_shared(
                                (const char*)st->Bhi + boff));
#pragma unroll
                for (int e = 0; e < 2; e++)
#pragma unroll
                    for (int ms = 0; ms < 2; ms++)
                        mma_f16(acc[ms][p * 2 + e], ah[ms], bh[e], bh[e + 2]);
            }
        }
    };

    // paired-stage mainloop: one barrier per 2 k-stages
    for (int p = 0; p < NKT / 2; p++) {
        asm volatile("cp.async.wait_group 1;" ::: "memory");
        __syncthreads();
        issue_stage(2 * p + 3);  // slot (2p+3)%5 — consumed at pair p-1
        issue_stage(2 * p + 4);  // slot (2p+4)%5 ≡ (2p-1)%5 — consumed at pair p-1
        compute_stage(2 * p);
        compute_stage(2 * p + 1);
    }

    // ---------------- fused gate epilogue (z staged in stage smem) ----------------
    __syncthreads();
    float* zsm = reinterpret_cast<float*>(smem_raw);  // [128][LDZ] = 67.6KB <= 100KB

#pragma unroll
    for (int ms = 0; ms < 2; ms++)
#pragma unroll
        for (int ns = 0; ns < 8; ns++) {
            int row = mw + ms * 16 + r;
            int col = nw + ns * 8 + 2 * q;
            *(float2*)&zsm[row * LDZ + col] = make_float2(acc[ms][ns][0], acc[ms][ns][1]);
            *(float2*)&zsm[(row + 8) * LDZ + col] = make_float2(acc[ms][ns][2], acc[ms][ns][3]);
        }
    __syncthreads();

    {
        const int ul = tid & 31;             // local unit 0..31
        const int u = blockIdx.x * 32 + ul;  // global unit
        const float bi = bias[u];
        const float bf = bias[512 + u];
        const float bg = bias[1024 + u];
        const float bo = bias[1536 + u];
        const float pwi = pw[u * 3 + 0];
        const float pwf = pw[u * 3 + 1];
        const float pwo = pw[u * 3 + 2];
#pragma unroll
        for (int it = 0; it < 16; it++) {
            int row = (tid >> 5) * 16 + it;
            int m = m0 + row;
            float4 zz = *reinterpret_cast<const float4*>(&zsm[row * LDZ + ul * 4]);
            float cprev = c_tm1[(size_t)m * UU + u];
            float iv = sigf(zz.x + bi + cprev * pwi);
            float fv = sigf(zz.y + bf + cprev * pwf);
            float gv = tanhf(zz.z + bg);
            float cc = fv * cprev + iv * gv;
            float ov = sigf(zz.w + bo + cc * pwo);
            out[(size_t)m * UU + u] = ov * tanhf(cc);
            out[(size_t)MM * UU + (size_t)m * UU + u] = cc;
        }
    }
}

// ---------------- launch ----------------
extern "C" void kernel_launch(void* const* d_in, const int* in_sizes, int n_in,
                              void* d_out, int out_size) {
    const float* x    = (const float*)d_in[0];
    const float* h    = (const float*)d_in[1];
    const float* c    = (const float*)d_in[2];
    const float* Wk   = (const float*)d_in[3];
    const float* Wr   = (const float*)d_in[4];
    const float* pw   = (const float*)d_in[5];
    const float* bias = (const float*)d_in[6];
    float* out = (float*)d_out;

    cudaFuncSetAttribute(lstm_gemm_kernel, cudaFuncAttributeMaxDynamicSharedMemorySize,
                         (int)(NSTAGES * sizeof(Stage)));

    prep_A_kernel<<<(MM * KK / 8) / 256, 256>>>(x, h);
    prep_B_kernel<<<dim3(NN / 32, KK / 32), dim3(32, 8)>>>(Wk, Wr);
    lstm_gemm_kernel<<<dim3(NN / BN, MM / BM), 256, NSTAGES * sizeof(Stage)>>>(c, pw, bias, out);
}

// round 13
// speedup vs baseline: 1.1213x; 1.0362x over previous
#include <cuda_runtime.h>
#include <cuda_bf16.h>
#include <cuda_fp16.h>
#include <cstdint>

// ---------------- problem dims ----------------
#define MM 16384
#define DD 512
#define UU 512
#define KK 1024
#define NN 2048

// ---------------- GEMM tiling ----------------
#define BM 128
#define BN 128
#define BK 32
#define NKT (KK / BK)            // 32
#define NSTAGES 5                // ring of 5, consumed 2 per barrier
#define LDT 40                   // fp16 tile leading dim (halfwords): 80B rows

// ---------------- device scratch ----------------
__device__ __align__(16) __half g_A[(size_t)MM * KK];    // fp16(a)
__device__ __align__(16) __half g_Bhi[(size_t)NN * KK];  // fp16(b), permuted rows

// ---------------- merged prep: blocks [0,8192) do A, [8192, 10240) do B ----------------
#define PREP_A_BLOCKS (MM * KK / 8 / 256)   // 8192
#define PREP_B_BLOCKS ((NN / 32) * (KK / 32))  // 2048

__global__ void __launch_bounds__(256) prep_kernel(const float* __restrict__ x,
                                                   const float* __restrict__ h,
                                                   const float* __restrict__ Wk,
                                                   const float* __restrict__ Wr) {
    if (blockIdx.x < PREP_A_BLOCKS) {
        int gi = blockIdx.x * 256 + threadIdx.x;
        int b = gi >> 7;
        int k0 = (gi & 127) * 8;
        const float* src = (k0 < DD) ? (x + (size_t)b * DD + k0)
                                     : (h + (size_t)b * UU + (k0 - DD));
        float4 v0 = *reinterpret_cast<const float4*>(src);
        float4 v1 = *reinterpret_cast<const float4*>(src + 4);
        float v[8] = {v0.x, v0.y, v0.z, v0.w, v1.x, v1.y, v1.z, v1.w};
        __half hh[8];
#pragma unroll
        for (int j = 0; j < 8; j++) hh[j] = __float2half_rn(v[j]);
        *reinterpret_cast<uint4*>(&g_A[(size_t)b * KK + k0]) = *reinterpret_cast<uint4*>(hh);
    } else {
        __shared__ float t[32][33];
        int bb = blockIdx.x - PREP_A_BLOCKS;
        int n0 = (bb & 63) * 32, k0 = (bb >> 6) * 32;
        int tn = threadIdx.x & 31, tk = threadIdx.x >> 5;  // 32 x 8
#pragma unroll
        for (int j = 0; j < 32; j += 8) {
            int k = k0 + tk + j;
            float v = (k < DD) ? Wk[(size_t)k * NN + n0 + tn]
                               : Wr[(size_t)(k - DD) * NN + n0 + tn];
            t[tk + j][tn] = v;
        }
        __syncthreads();
#pragma unroll
        for (int j = 0; j < 32; j += 8) {
            int n = n0 + tk + j;
            int k = k0 + tn;
            int p = ((n & 511) << 2) + (n >> 9);  // unit*4 + gate
            g_Bhi[(size_t)p * KK + k] = __float2half_rn(t[tn][tk + j]);
        }
    }
}

// ---------------- fused GEMM (single-pass f16, paired-stage sync) + gates ----------------
struct Stage {
    __half A[BM * LDT];     // 10240 B
    __half Bhi[BN * LDT];   // 10240 B
};  // 20480 B

__device__ __forceinline__ void cp_async16(void* dst, const void* src) {
    unsigned d = (unsigned)__cvta_generic_to_shared(dst);
    asm volatile("cp.async.cg.shared.global [%0], [%1], 16;" :: "r"(d), "l"(src) : "memory");
}

__device__ __forceinline__ void ldsm_x4(unsigned r[4], uint32_t addr) {
    asm volatile("ldmatrix.sync.aligned.m8n8.x4.shared.b16 {%0,%1,%2,%3}, [%4];"
                 : "=r"(r[0]), "=r"(r[1]), "=r"(r[2]), "=r"(r[3]) : "r"(addr));
}

__device__ __forceinline__ void mma_f16(float c[4], const unsigned a[4],
                                        unsigned b0, unsigned b1) {
    asm volatile(
        "mma.sync.aligned.m16n8k16.row.col.f32.f16.f16.f32 "
        "{%0,%1,%2,%3}, {%4,%5,%6,%7}, {%8,%9}, {%0,%1,%2,%3};"
        : "+f"(c[0]), "+f"(c[1]), "+f"(c[2]), "+f"(c[3])
        : "r"(a[0]), "r"(a[1]), "r"(a[2]), "r"(a[3]), "r"(b0), "r"(b1));
}

__device__ __forceinline__ float sigf(float x) { return 1.0f / (1.0f + __expf(-x)); }
__device__ __forceinline__ float ftanh(float x) {
    float t = __expf(2.0f * x);
    return __fdividef(t - 1.0f, t + 1.0f);
}

#define LDZ 132  // padded z stride in floats (multiple of 4: float4-aligned rows)

__global__ void __launch_bounds__(256, 2)
lstm_gemm_kernel(const float* __restrict__ c_tm1,
                 const float* __restrict__ pw,
                 const float* __restrict__ bias,
                 float* __restrict__ out) {
    extern __shared__ __align__(16) unsigned char smem_raw[];
    Stage* stages = reinterpret_cast<Stage*>(smem_raw);

    const int tid = threadIdx.x;
    const int lane = tid & 31;
    const int wid = tid >> 5;        // 0..7
    const int mw = (wid >> 1) * 32;  // 4 warps in M
    const int nw = (wid & 1) * 64;   // 2 warps in N
    const int m0 = blockIdx.y * BM;
    const int n0 = blockIdx.x * BN;
    const int r = lane >> 2, q = lane & 3;

    const int lrow = (lane & 7) + ((lane >> 3) & 1) * 8;
    const int lkof = (lane >> 4) * 16;  // bytes

    // issue loads for k-stage s into ring slot s % NSTAGES; one commit per call
    auto issue_stage = [&](int s) {
        if (s < NKT) {
            Stage* st = &stages[s % NSTAGES];
            int k0 = s * BK;
#pragma unroll
            for (int i = 0; i < 2; i++) {
                int c = tid + i * 256;
                int row = c >> 2, seg = c & 3;
                cp_async16(&st->A[row * LDT + seg * 8],
                           &g_A[(size_t)(m0 + row) * KK + k0 + seg * 8]);
                cp_async16(&st->Bhi[row * LDT + seg * 8],
                           &g_Bhi[(size_t)(n0 + row) * KK + k0 + seg * 8]);
            }
        }
        asm volatile("cp.async.commit_group;" ::: "memory");
    };

    float acc[2][8][4];
#pragma unroll
    for (int a = 0; a < 2; a++)
#pragma unroll
        for (int b = 0; b < 8; b++)
#pragma unroll
            for (int c = 0; c < 4; c++) acc[a][b][c] = 0.0f;

    issue_stage(0);
    issue_stage(1);
    issue_stage(2);

    // compute one k-stage from ring slot
    auto compute_stage = [&](int s) {
        const Stage* st = &stages[s % NSTAGES];
#pragma unroll
        for (int kk = 0; kk < BK; kk += 16) {
            unsigned ah[2][4];
#pragma unroll
            for (int ms = 0; ms < 2; ms++) {
                uint32_t boff = (uint32_t)(((mw + ms * 16 + lrow) * LDT + kk) * 2 + lkof);
                ldsm_x4(ah[ms], (unsigned)__cvta_generic_to_shared(
                                    (const char*)st->A + boff));
            }
#pragma unroll
            for (int p = 0; p < 4; p++) {
                uint32_t boff = (uint32_t)(((nw + p * 16 + lrow) * LDT + kk) * 2 + lkof);
                unsigned bh[4];
                ldsm_x4(bh, (unsigned)__cvta_generic_to_shared(
                                (const char*)st->Bhi + boff));
#pragma unroll
                for (int e = 0; e < 2; e++)
#pragma unroll
                    for (int ms = 0; ms < 2; ms++)
                        mma_f16(acc[ms][p * 2 + e], ah[ms], bh[e], bh[e + 2]);
            }
        }
    };

    // paired-stage mainloop: one barrier per 2 k-stages; cp.async issue interleaved
    for (int p = 0; p < NKT / 2; p++) {
        asm volatile("cp.async.wait_group 1;" ::: "memory");
        __syncthreads();
        issue_stage(2 * p + 3);  // slot (2p+3)%5 — consumed at pair p-1
        compute_stage(2 * p);
        issue_stage(2 * p + 4);  // slot (2p+4)%5 ≡ (2p-1)%5 — consumed at pair p-1
        compute_stage(2 * p + 1);
    }

    // ---------------- fused gate epilogue (z staged in stage smem) ----------------
    __syncthreads();
    float* zsm = reinterpret_cast<float*>(smem_raw);  // [128][LDZ] = 67.6KB <= 100KB

#pragma unroll
    for (int ms = 0; ms < 2; ms++)
#pragma unroll
        for (int ns = 0; ns < 8; ns++) {
            int row = mw + ms * 16 + r;
            int col = nw + ns * 8 + 2 * q;
            *(float2*)&zsm[row * LDZ + col] = make_float2(acc[ms][ns][0], acc[ms][ns][1]);
            *(float2*)&zsm[(row + 8) * LDZ + col] = make_float2(acc[ms][ns][2], acc[ms][ns][3]);
        }
    __syncthreads();

    {
        const int ul = tid & 31;             // local unit 0..31
        const int u = blockIdx.x * 32 + ul;  // global unit
        const float bi = bias[u];
        const float bf = bias[512 + u];
        const float bg = bias[1024 + u];
        const float bo = bias[1536 + u];
        const float pwi = pw[u * 3 + 0];
        const float pwf = pw[u * 3 + 1];
        const float pwo = pw[u * 3 + 2];
#pragma unroll
        for (int it = 0; it < 16; it++) {
            int row = (tid >> 5) * 16 + it;
            int m = m0 + row;
            float4 zz = *reinterpret_cast<const float4*>(&zsm[row * LDZ + ul * 4]);
            float cprev = c_tm1[(size_t)m * UU + u];
            float iv = sigf(zz.x + bi + cprev * pwi);
            float fv = sigf(zz.y + bf + cprev * pwf);
            float gv = ftanh(zz.z + bg);
            float cc = fv * cprev + iv * gv;
            float ov = sigf(zz.w + bo + cc * pwo);
            out[(size_t)m * UU + u] = ov * ftanh(cc);
            out[(size_t)MM * UU + (size_t)m * UU + u] = cc;
        }
    }
}

// ---------------- launch ----------------
extern "C" void kernel_launch(void* const* d_in, const int* in_sizes, int n_in,
                              void* d_out, int out_size) {
    const float* x    = (const float*)d_in[0];
    const float* h    = (const float*)d_in[1];
    const float* c    = (const float*)d_in[2];
    const float* Wk   = (const float*)d_in[3];
    const float* Wr   = (const float*)d_in[4];
    const float* pw   = (const float*)d_in[5];
    const float* bias = (const float*)d_in[6];
    float* out = (float*)d_out;

    cudaFuncSetAttribute(lstm_gemm_kernel, cudaFuncAttributeMaxDynamicSharedMemorySize,
                         (int)(NSTAGES * sizeof(Stage)));

    prep_kernel<<<PREP_A_BLOCKS + PREP_B_BLOCKS, 256>>>(x, h, Wk, Wr);
    lstm_gemm_kernel<<<dim3(NN / BN, MM / BM), 256, NSTAGES * sizeof(Stage)>>>(c, pw, bias, out);
}

// round 14
// speedup vs baseline: 1.1789x; 1.0514x over previous
#include <cuda_runtime.h>
#include <cuda_bf16.h>
#include <cuda_fp16.h>
#include <cstdint>

// ---------------- problem dims ----------------
#define MM 16384
#define DD 512
#define UU 512
#define KK 1024
#define NN 2048

// ---------------- GEMM tiling ----------------
#define BM 128
#define BN 128
#define BK 32
#define NKT (KK / BK)            // 32
#define NSTAGES 5                // ring of 5, consumed 2 per barrier
#define LDT 40                   // fp16 tile leading dim (halfwords): 80B rows

// ---------------- device scratch ----------------
__device__ __align__(16) __half g_A[(size_t)MM * KK];    // fp16(a)
__device__ __align__(16) __half g_Bhi[(size_t)NN * KK];  // fp16(b), permuted rows

// ---------------- merged prep: blocks [0,8192) do A, [8192, 10240) do B ----------------
#define PREP_A_BLOCKS (MM * KK / 8 / 256)      // 8192
#define PREP_B_BLOCKS ((NN / 32) * (KK / 32))  // 2048

__global__ void __launch_bounds__(256) prep_kernel(const float* __restrict__ x,
                                                   const float* __restrict__ h,
                                                   const float* __restrict__ Wk,
                                                   const float* __restrict__ Wr) {
    if (blockIdx.x < PREP_A_BLOCKS) {
        int gi = blockIdx.x * 256 + threadIdx.x;
        int b = gi >> 7;
        int k0 = (gi & 127) * 8;
        const float* src = (k0 < DD) ? (x + (size_t)b * DD + k0)
                                     : (h + (size_t)b * UU + (k0 - DD));
        float4 v0 = *reinterpret_cast<const float4*>(src);
        float4 v1 = *reinterpret_cast<const float4*>(src + 4);
        float v[8] = {v0.x, v0.y, v0.z, v0.w, v1.x, v1.y, v1.z, v1.w};
        __half hh[8];
#pragma unroll
        for (int j = 0; j < 8; j++) hh[j] = __float2half_rn(v[j]);
        *reinterpret_cast<uint4*>(&g_A[(size_t)b * KK + k0]) = *reinterpret_cast<uint4*>(hh);
    } else {
        __shared__ float t[32][33];
        int bb = blockIdx.x - PREP_A_BLOCKS;
        int n0 = (bb & 63) * 32, k0 = (bb >> 6) * 32;
        int tn = threadIdx.x & 31, tk = threadIdx.x >> 5;  // 32 x 8
#pragma unroll
        for (int j = 0; j < 32; j += 8) {
            int k = k0 + tk + j;
            float v = (k < DD) ? Wk[(size_t)k * NN + n0 + tn]
                               : Wr[(size_t)(k - DD) * NN + n0 + tn];
            t[tk + j][tn] = v;
        }
        __syncthreads();
#pragma unroll
        for (int j = 0; j < 32; j += 8) {
            int n = n0 + tk + j;
            int k = k0 + tn;
            int p = ((n & 511) << 2) + (n >> 9);  // unit*4 + gate
            g_Bhi[(size_t)p * KK + k] = __float2half_rn(t[tn][tk + j]);
        }
    }
}

// ---------------- fused GEMM (single-pass f16, 32 warps/SM) + gates ----------------
struct Stage {
    __half A[BM * LDT];     // 10240 B
    __half Bhi[BN * LDT];   // 10240 B
};  // 20480 B

__device__ __forceinline__ void cp_async16(void* dst, const void* src) {
    unsigned d = (unsigned)__cvta_generic_to_shared(dst);
    asm volatile("cp.async.cg.shared.global [%0], [%1], 16;" :: "r"(d), "l"(src) : "memory");
}

__device__ __forceinline__ void ldsm_x4(unsigned r[4], uint32_t addr) {
    asm volatile("ldmatrix.sync.aligned.m8n8.x4.shared.b16 {%0,%1,%2,%3}, [%4];"
                 : "=r"(r[0]), "=r"(r[1]), "=r"(r[2]), "=r"(r[3]) : "r"(addr));
}

__device__ __forceinline__ void mma_f16(float c[4], const unsigned a[4],
                                        unsigned b0, unsigned b1) {
    asm volatile(
        "mma.sync.aligned.m16n8k16.row.col.f32.f16.f16.f32 "
        "{%0,%1,%2,%3}, {%4,%5,%6,%7}, {%8,%9}, {%0,%1,%2,%3};"
        : "+f"(c[0]), "+f"(c[1]), "+f"(c[2]), "+f"(c[3])
        : "r"(a[0]), "r"(a[1]), "r"(a[2]), "r"(a[3]), "r"(b0), "r"(b1));
}

__device__ __forceinline__ float sigf(float x) { return 1.0f / (1.0f + __expf(-x)); }
__device__ __forceinline__ float ftanh(float x) {
    float t = __expf(2.0f * x);
    return __fdividef(t - 1.0f, t + 1.0f);
}

#define LDZ 132  // padded z stride in floats (multiple of 4: float4-aligned rows)

__global__ void __launch_bounds__(512, 2)
lstm_gemm_kernel(const float* __restrict__ c_tm1,
                 const float* __restrict__ pw,
                 const float* __restrict__ bias,
                 float* __restrict__ out) {
    extern __shared__ __align__(16) unsigned char smem_raw[];
    Stage* stages = reinterpret_cast<Stage*>(smem_raw);

    const int tid = threadIdx.x;
    const int lane = tid & 31;
    const int wid = tid >> 5;        // 0..15
    const int mw = (wid >> 2) * 32;  // 4 warps in M
    const int nw = (wid & 3) * 32;   // 4 warps in N
    const int m0 = blockIdx.y * BM;
    const int n0 = blockIdx.x * BN;
    const int r = lane >> 2, q = lane & 3;

    const int lrow = (lane & 7) + ((lane >> 3) & 1) * 8;
    const int lkof = (lane >> 4) * 16;  // bytes

    // per-warp ldsm byte offsets (hoisted; kk term added in-loop)
    const uint32_t a_off0 = (uint32_t)(((mw + lrow) * LDT) * 2 + lkof);
    const uint32_t a_off1 = a_off0 + 16 * LDT * 2;
    const uint32_t b_off0 = (uint32_t)(((nw + lrow) * LDT) * 2 + lkof);
    const uint32_t b_off1 = b_off0 + 16 * LDT * 2;

    // issue loads for k-stage s into ring slot s % NSTAGES; one commit per call
    auto issue_stage = [&](int s) {
        if (s < NKT) {
            Stage* st = &stages[s % NSTAGES];
            int k0 = s * BK;
            int row = tid >> 2, seg = tid & 3;  // 512 chunks each, 1/thread
            cp_async16(&st->A[row * LDT + seg * 8],
                       &g_A[(size_t)(m0 + row) * KK + k0 + seg * 8]);
            cp_async16(&st->Bhi[row * LDT + seg * 8],
                       &g_Bhi[(size_t)(n0 + row) * KK + k0 + seg * 8]);
        }
        asm volatile("cp.async.commit_group;" ::: "memory");
    };

    float acc[2][4][4];
#pragma unroll
    for (int a = 0; a < 2; a++)
#pragma unroll
        for (int b = 0; b < 4; b++)
#pragma unroll
            for (int c = 0; c < 4; c++) acc[a][b][c] = 0.0f;

    issue_stage(0);
    issue_stage(1);
    issue_stage(2);

    // compute one k-stage from ring slot
    auto compute_stage = [&](int s) {
        const Stage* st = &stages[s % NSTAGES];
        uint32_t abase = (uint32_t)__cvta_generic_to_shared(st->A);
        uint32_t bbase = (uint32_t)__cvta_generic_to_shared(st->Bhi);
#pragma unroll
        for (int kk = 0; kk < BK; kk += 16) {
            unsigned ah[2][4];
            ldsm_x4(ah[0], abase + a_off0 + kk * 2);
            ldsm_x4(ah[1], abase + a_off1 + kk * 2);
#pragma unroll
            for (int p = 0; p < 2; p++) {
                unsigned bh[4];
                ldsm_x4(bh, bbase + (p ? b_off1 : b_off0) + kk * 2);
#pragma unroll
                for (int e = 0; e < 2; e++)
#pragma unroll
                    for (int ms = 0; ms < 2; ms++)
                        mma_f16(acc[ms][p * 2 + e], ah[ms], bh[e], bh[e + 2]);
            }
        }
    };

    // paired-stage mainloop: one barrier per 2 k-stages; cp.async issue interleaved
    for (int p = 0; p < NKT / 2; p++) {
        asm volatile("cp.async.wait_group 1;" ::: "memory");
        __syncthreads();
        issue_stage(2 * p + 3);  // slot (2p+3)%5 — consumed at pair p-1
        compute_stage(2 * p);
        issue_stage(2 * p + 4);  // slot (2p+4)%5 ≡ (2p-1)%5 — consumed at pair p-1
        compute_stage(2 * p + 1);
    }

    // ---------------- fused gate epilogue (z staged in stage smem) ----------------
    __syncthreads();
    float* zsm = reinterpret_cast<float*>(smem_raw);  // [128][LDZ] = 67.6KB <= 100KB

#pragma unroll
    for (int ms = 0; ms < 2; ms++)
#pragma unroll
        for (int ns = 0; ns < 4; ns++) {
            int row = mw + ms * 16 + r;
            int col = nw + ns * 8 + 2 * q;
            *(float2*)&zsm[row * LDZ + col] = make_float2(acc[ms][ns][0], acc[ms][ns][1]);
            *(float2*)&zsm[(row + 8) * LDZ + col] = make_float2(acc[ms][ns][2], acc[ms][ns][3]);
        }
    __syncthreads();

    {
        const int ul = tid & 31;             // local unit 0..31
        const int u = blockIdx.x * 32 + ul;  // global unit
        const float bi = bias[u];
        const float bf = bias[512 + u];
        const float bg = bias[1024 + u];
        const float bo = bias[1536 + u];
        const float pwi = pw[u * 3 + 0];
        const float pwf = pw[u * 3 + 1];
        const float pwo = pw[u * 3 + 2];
#pragma unroll
        for (int it = 0; it < 8; it++) {
            int row = (tid >> 5) * 8 + it;
            int m = m0 + row;
            float4 zz = *reinterpret_cast<const float4*>(&zsm[row * LDZ + ul * 4]);
            float cprev = c_tm1[(size_t)m * UU + u];
            float iv = sigf(zz.x + bi + cprev * pwi);
            float fv = sigf(zz.y + bf + cprev * pwf);
            float gv = ftanh(zz.z + bg);
            float cc = fv * cprev + iv * gv;
            float ov = sigf(zz.w + bo + cc * pwo);
            out[(size_t)m * UU + u] = ov * ftanh(cc);
            out[(size_t)MM * UU + (size_t)m * UU + u] = cc;
        }
    }
}

// ---------------- launch ----------------
extern "C" void kernel_launch(void* const* d_in, const int* in_sizes, int n_in,
                              void* d_out, int out_size) {
    const float* x    = (const float*)d_in[0];
    const float* h    = (const float*)d_in[1];
    const float* c    = (const float*)d_in[2];
    const float* Wk   = (const float*)d_in[3];
    const float* Wr   = (const float*)d_in[4];
    const float* pw   = (const float*)d_in[5];
    const float* bias = (const float*)d_in[6];
    float* out = (float*)d_out;

    cudaFuncSetAttribute(lstm_gemm_kernel, cudaFuncAttributeMaxDynamicSharedMemorySize,
                         (int)(NSTAGES * sizeof(Stage)));

    prep_kernel<<<PREP_A_BLOCKS + PREP_B_BLOCKS, 256>>>(x, h, Wk, Wr);
    lstm_gemm_kernel<<<dim3(NN / BN, MM / BM), 512, NSTAGES * sizeof(Stage)>>>(c, pw, bias, out);
}

// round 15
// speedup vs baseline: 1.3433x; 1.1394x over previous
#include <cuda_runtime.h>
#include <cuda_bf16.h>
#include <cuda_fp16.h>
#include <cstdint>

// ---------------- problem dims ----------------
#define MM 16384
#define DD 512
#define UU 512
#define KK 1024
#define NN 2048

// ---------------- GEMM tiling ----------------
#define BM 128
#define BN 128
#define BK 32
#define NKT (KK / BK)            // 32
#define NSTAGES 5                // ring of 5, consumed 2 per barrier
#define LDT 40                   // fp16 tile leading dim (halfwords): 80B rows

// ---------------- device scratch ----------------
__device__ __align__(16) __half g_A[(size_t)MM * KK];    // fp16(a)
__device__ __align__(16) __half g_Bhi[(size_t)NN * KK];  // fp16(b), permuted rows

// ---------------- merged prep: blocks [0,8192) do A, [8192, 10240) do B ----------------
#define PREP_A_BLOCKS (MM * KK / 8 / 256)      // 8192
#define PREP_B_BLOCKS ((NN / 32) * (KK / 32))  // 2048

__global__ void __launch_bounds__(256) prep_kernel(const float* __restrict__ x,
                                                   const float* __restrict__ h,
                                                   const float* __restrict__ Wk,
                                                   const float* __restrict__ Wr) {
    if (blockIdx.x < PREP_A_BLOCKS) {
        int gi = blockIdx.x * 256 + threadIdx.x;
        int b = gi >> 7;
        int k0 = (gi & 127) * 8;
        const float* src = (k0 < DD) ? (x + (size_t)b * DD + k0)
                                     : (h + (size_t)b * UU + (k0 - DD));
        float4 v0 = *reinterpret_cast<const float4*>(src);
        float4 v1 = *reinterpret_cast<const float4*>(src + 4);
        float v[8] = {v0.x, v0.y, v0.z, v0.w, v1.x, v1.y, v1.z, v1.w};
        __half hh[8];
#pragma unroll
        for (int j = 0; j < 8; j++) hh[j] = __float2half_rn(v[j]);
        *reinterpret_cast<uint4*>(&g_A[(size_t)b * KK + k0]) = *reinterpret_cast<uint4*>(hh);
    } else {
        __shared__ float t[32][33];
        int bb = blockIdx.x - PREP_A_BLOCKS;
        int n0 = (bb & 63) * 32, k0 = (bb >> 6) * 32;
        int tn = threadIdx.x & 31, tk = threadIdx.x >> 5;  // 32 x 8
#pragma unroll
        for (int j = 0; j < 32; j += 8) {
            int k = k0 + tk + j;
            float v = (k < DD) ? Wk[(size_t)k * NN + n0 + tn]
                               : Wr[(size_t)(k - DD) * NN + n0 + tn];
            t[tk + j][tn] = v;
        }
        __syncthreads();
#pragma unroll
        for (int j = 0; j < 32; j += 8) {
            int n = n0 + tk + j;
            int k = k0 + tn;
            int p = ((n & 511) << 2) + (n >> 9);  // unit*4 + gate
            g_Bhi[(size_t)p * KK + k] = __float2half_rn(t[tn][tk + j]);
        }
    }
}

// ---------------- fused GEMM (single-pass f16, fully unrolled ring) + gates ----------------
struct Stage {
    __half A[BM * LDT];     // 10240 B
    __half Bhi[BN * LDT];   // 10240 B
};  // 20480 B

__device__ __forceinline__ void cp_async16(void* dst, const void* src) {
    unsigned d = (unsigned)__cvta_generic_to_shared(dst);
    asm volatile("cp.async.cg.shared.global [%0], [%1], 16;" :: "r"(d), "l"(src) : "memory");
}

__device__ __forceinline__ void ldsm_x4(unsigned r[4], uint32_t addr) {
    asm volatile("ldmatrix.sync.aligned.m8n8.x4.shared.b16 {%0,%1,%2,%3}, [%4];"
                 : "=r"(r[0]), "=r"(r[1]), "=r"(r[2]), "=r"(r[3]) : "r"(addr));
}

__device__ __forceinline__ void mma_f16(float c[4], const unsigned a[4],
                                        unsigned b0, unsigned b1) {
    asm volatile(
        "mma.sync.aligned.m16n8k16.row.col.f32.f16.f16.f32 "
        "{%0,%1,%2,%3}, {%4,%5,%6,%7}, {%8,%9}, {%0,%1,%2,%3};"
        : "+f"(c[0]), "+f"(c[1]), "+f"(c[2]), "+f"(c[3])
        : "r"(a[0]), "r"(a[1]), "r"(a[2]), "r"(a[3]), "r"(b0), "r"(b1));
}

__device__ __forceinline__ float sigf(float x) { return 1.0f / (1.0f + __expf(-x)); }
__device__ __forceinline__ float ftanh(float x) {
    float t = __expf(2.0f * x);
    return __fdividef(t - 1.0f, t + 1.0f);
}

#define LDZ 132  // padded z stride in floats (multiple of 4: float4-aligned rows)

__global__ void __launch_bounds__(512, 2)
lstm_gemm_kernel(const float* __restrict__ c_tm1,
                 const float* __restrict__ pw,
                 const float* __restrict__ bias,
                 float* __restrict__ out) {
    extern __shared__ __align__(16) unsigned char smem_raw[];
    Stage* stages = reinterpret_cast<Stage*>(smem_raw);

    const int tid = threadIdx.x;
    const int lane = tid & 31;
    const int wid = tid >> 5;        // 0..15
    const int mw = (wid >> 2) * 32;  // 4 warps in M
    const int nw = (wid & 3) * 32;   // 4 warps in N
    const int m0 = blockIdx.y * BM;
    const int n0 = blockIdx.x * BN;
    const int r = lane >> 2, q = lane & 3;

    const int lrow = (lane & 7) + ((lane >> 3) & 1) * 8;
    const int lkof = (lane >> 4) * 16;  // bytes

    // hoisted bases
    const uint32_t smem_base = (uint32_t)__cvta_generic_to_shared(smem_raw);
    const uint32_t a_off0 = smem_base + (uint32_t)(((mw + lrow) * LDT) * 2 + lkof);
    const uint32_t a_off1 = a_off0 + 16 * LDT * 2;
    const uint32_t b_off0 = smem_base + (uint32_t)(10240 + ((nw + lrow) * LDT) * 2 + lkof);
    const uint32_t b_off1 = b_off0 + 16 * LDT * 2;

    const int ld_row = tid >> 2, ld_seg = tid & 3;
    const size_t a_src_base = (size_t)(m0 + ld_row) * KK + ld_seg * 8;
    const size_t b_src_base = (size_t)(n0 + ld_row) * KK + ld_seg * 8;
    const int ld_soff = ld_row * LDT + ld_seg * 8;

    float acc[2][4][4];
#pragma unroll
    for (int a = 0; a < 2; a++)
#pragma unroll
        for (int b = 0; b < 4; b++)
#pragma unroll
            for (int c = 0; c < 4; c++) acc[a][b][c] = 0.0f;

    // issue k-stage s into ring slot s % NSTAGES (call with compile-time s)
    auto issue_stage = [&](int s) {
        if (s < NKT) {
            Stage* st = &stages[s % NSTAGES];
            cp_async16(&st->A[ld_soff], &g_A[a_src_base + s * BK]);
            cp_async16(&st->Bhi[ld_soff], &g_Bhi[b_src_base + s * BK]);
        }
        asm volatile("cp.async.commit_group;" ::: "memory");
    };

    // compute k-stage from ring slot (call with compile-time s)
    auto compute_stage = [&](int s) {
        const uint32_t sbo = (uint32_t)((s % NSTAGES) * sizeof(Stage));
#pragma unroll
        for (int kk = 0; kk < BK; kk += 16) {
            unsigned ah[2][4];
            ldsm_x4(ah[0], a_off0 + sbo + kk * 2);
            ldsm_x4(ah[1], a_off1 + sbo + kk * 2);
#pragma unroll
            for (int p = 0; p < 2; p++) {
                unsigned bh[4];
                ldsm_x4(bh, (p ? b_off1 : b_off0) + sbo + kk * 2);
#pragma unroll
                for (int e = 0; e < 2; e++)
#pragma unroll
                    for (int ms = 0; ms < 2; ms++)
                        mma_f16(acc[ms][p * 2 + e], ah[ms], bh[e], bh[e + 2]);
            }
        }
    };

    issue_stage(0);
    issue_stage(1);
    issue_stage(2);

    // fully unrolled paired-stage mainloop: all ring indices constant-fold
#pragma unroll
    for (int p = 0; p < NKT / 2; p++) {
        asm volatile("cp.async.wait_group 1;" ::: "memory");
        __syncthreads();
        issue_stage(2 * p + 3);  // slot (2p+3)%5 — consumed at pair p-1
        compute_stage(2 * p);
        issue_stage(2 * p + 4);  // slot (2p+4)%5 ≡ (2p-1)%5 — consumed at pair p-1
        compute_stage(2 * p + 1);
    }

    // ---------------- fused gate epilogue (z staged in stage smem) ----------------
    __syncthreads();
    float* zsm = reinterpret_cast<float*>(smem_raw);  // [128][LDZ] = 67.6KB <= 100KB

#pragma unroll
    for (int ms = 0; ms < 2; ms++)
#pragma unroll
        for (int ns = 0; ns < 4; ns++) {
            int row = mw + ms * 16 + r;
            int col = nw + ns * 8 + 2 * q;
            *(float2*)&zsm[row * LDZ + col] = make_float2(acc[ms][ns][0], acc[ms][ns][1]);
            *(float2*)&zsm[(row + 8) * LDZ + col] = make_float2(acc[ms][ns][2], acc[ms][ns][3]);
        }
    __syncthreads();

    {
        const int ul = tid & 31;             // local unit 0..31
        const int u = blockIdx.x * 32 + ul;  // global unit
        const float bi = bias[u];
        const float bf = bias[512 + u];
        const float bg = bias[1024 + u];
        const float bo = bias[1536 + u];
        const float pwi = pw[u * 3 + 0];
        const float pwf = pw[u * 3 + 1];
        const float pwo = pw[u * 3 + 2];
#pragma unroll
        for (int it = 0; it < 8; it++) {
            int row = (tid >> 5) * 8 + it;
            int m = m0 + row;
            float4 zz = *reinterpret_cast<const float4*>(&zsm[row * LDZ + ul * 4]);
            float cprev = c_tm1[(size_t)m * UU + u];
            float iv = sigf(zz.x + bi + cprev * pwi);
            float fv = sigf(zz.y + bf + cprev * pwf);
            float gv = ftanh(zz.z + bg);
            float cc = fv * cprev + iv * gv;
            float ov = sigf(zz.w + bo + cc * pwo);
            out[(size_t)m * UU + u] = ov * ftanh(cc);
            out[(size_t)MM * UU + (size_t)m * UU + u] = cc;
        }
    }
}

// ---------------- launch ----------------
extern "C" void kernel_launch(void* const* d_in, const int* in_sizes, int n_in,
                              void* d_out, int out_size) {
    const float* x    = (const float*)d_in[0];
    const float* h    = (const float*)d_in[1];
    const float* c    = (const float*)d_in[2];
    const float* Wk   = (const float*)d_in[3];
    const float* Wr   = (const float*)d_in[4];
    const float* pw   = (const float*)d_in[5];
    const float* bias = (const float*)d_in[6];
    float* out = (float*)d_out;

    cudaFuncSetAttribute(lstm_gemm_kernel, cudaFuncAttributeMaxDynamicSharedMemorySize,
                         (int)(NSTAGES * sizeof(Stage)));

    prep_kernel<<<PREP_A_BLOCKS + PREP_B_BLOCKS, 256>>>(x, h, Wk, Wr);
    lstm_gemm_kernel<<<dim3(NN / BN, MM / BM), 512, NSTAGES * sizeof(Stage)>>>(c, pw, bias, out);
}